// round 15
// baseline (speedup 1.0000x reference)
#include <cuda_runtime.h>
#include <cuda_bf16.h>
#include <math.h>
#include <stdint.h>

#define NN 8192
#define PP 128
#define DD 256

// ---------------- device scratch (static globals — no runtime alloc) ----------
__device__ __nv_bfloat16 g_Mt[384 * NN];            // Mᵀ bf16: rows 0-127 = Pᵀ, 128-383 = Xnᵀ
__device__ float g_Spart[146 * 64 * 128];           // kh=1 partial tiles (4.8 MB)
__device__ unsigned int g_pflag[146];               // per-tile handoff flags (self-reset)
__device__ double g_acc[2];                         // 0: coherence, 1: structure+weight SSE
__device__ unsigned int g_sync;                     // prep barrier (reset by finisher)
__device__ unsigned int g_done;                     // finisher ticket (reset by finisher)

// ---------------------------------------------------------------------------
__device__ __forceinline__ uint32_t smem_u32(const void* p) {
    return (uint32_t)__cvta_generic_to_shared(p);
}

__device__ __forceinline__ float block_reduce_sum(float v) {
    __shared__ float red[16];
    int lane = threadIdx.x & 31;
    int wid  = threadIdx.x >> 5;
    #pragma unroll
    for (int o = 16; o > 0; o >>= 1) v += __shfl_xor_sync(0xffffffffu, v, o);
    if (lane == 0) red[wid] = v;
    __syncthreads();
    if (wid == 0) {
        int nw = (int)blockDim.x >> 5;
        v = (lane < nw) ? red[lane] : 0.0f;
        #pragma unroll
        for (int o = 8; o > 0; o >>= 1) v += __shfl_xor_sync(0xffffffffu, v, o);
    }
    return v;
}

// ---------------------------------------------------------------------------
#define STRUCT_PAIRS 128
#define GRAM_PAIRS 18
#define PAIRS (STRUCT_PAIRS + GRAM_PAIRS)     // 146 output tiles
#define GRID_MAIN (PAIRS * 2)                 // 292 CTAs, 2/SM forced -> all resident

#define KH  (NN / 2)                          // 4096 K per CTA
#define KT 64
#define NIT (KH / KT)                         // 64 K-tiles
#define APAD 72
#define SA_STAGE (64 * APAD)
#define SB_STAGE (128 * APAD)
#define SMEM_GEMM ((SA_STAGE + SB_STAGE) * 2 * 2)  // 55296
#define XS 259
#define SMEM_PREPF (64 * XS * 4 + 64 * 4)          // 66560
#define SMEM_ALL (SMEM_PREPF > SMEM_GEMM ? SMEM_PREPF : SMEM_GEMM)

#define PREP_TASKS 384     // 128 X-slabs + 256 P-tiles

__device__ __forceinline__ void ldmx4(uint32_t& r0, uint32_t& r1, uint32_t& r2,
                                      uint32_t& r3, uint32_t addr) {
    asm volatile("ldmatrix.sync.aligned.m8n8.x4.shared.b16 {%0,%1,%2,%3}, [%4];"
                 : "=r"(r0), "=r"(r1), "=r"(r2), "=r"(r3) : "r"(addr));
}
__device__ __forceinline__ void mma_bf16(float* c, uint32_t a0, uint32_t a1,
                                         uint32_t a2, uint32_t a3,
                                         uint32_t b0, uint32_t b1) {
    asm volatile(
        "mma.sync.aligned.m16n8k16.row.col.f32.bf16.bf16.f32 "
        "{%0,%1,%2,%3}, {%4,%5,%6,%7}, {%8,%9}, {%0,%1,%2,%3};"
        : "+f"(c[0]), "+f"(c[1]), "+f"(c[2]), "+f"(c[3])
        : "r"(a0), "r"(a1), "r"(a2), "r"(a3), "r"(b0), "r"(b1));
}

// ---- prep task bodies (512 threads) ----------------------------------------
__device__ __forceinline__ void prep_xslab(const float* __restrict__ X,
                                           char* dynsm, int xs) {
    int t = threadIdx.x;
    int lane = t & 31;
    int wrp  = t >> 5;
    int tx = t & 15;
    int ty2 = t >> 4;                  // 0..31
    float* tt = (float*)dynsm;
    float* sI = (float*)(dynsm + 64 * XS * 4);
    int kb = xs * 64;

    #pragma unroll
    for (int q = 0; q < 8; q++) {
        int c = t + q * 512;
        int row = c >> 6;
        int col = (c & 63) * 4;
        float4 v = *(const float4*)&X[(size_t)(kb + row) * DD + col];
        tt[row * XS + col + 0] = v.x;
        tt[row * XS + col + 1] = v.y;
        tt[row * XS + col + 2] = v.z;
        tt[row * XS + col + 3] = v.w;
    }
    __syncthreads();

    #pragma unroll
    for (int r4 = 0; r4 < 4; r4++) {
        int row = wrp * 4 + r4;
        float ss = 0.0f;
        #pragma unroll
        for (int j = 0; j < 8; j++) {
            float x = tt[row * XS + lane * 8 + j];
            ss += x * x;
        }
        #pragma unroll
        for (int o = 16; o > 0; o >>= 1) ss += __shfl_xor_sync(0xffffffffu, ss, o);
        if (lane == 0) sI[row] = 1.0f / fmaxf(sqrtf(ss), 1e-8f);
    }
    __syncthreads();

    #pragma unroll
    for (int dt = 0; dt < 4; dt++) {
        #pragma unroll
        for (int rr = ty2; rr < 64; rr += 32) {
            int cc = tx * 4;
            int sc = dt * 64 + rr;
            float f0 = tt[(cc + 0) * XS + sc] * sI[cc + 0];
            float f1 = tt[(cc + 1) * XS + sc] * sI[cc + 1];
            float f2 = tt[(cc + 2) * XS + sc] * sI[cc + 2];
            float f3 = tt[(cc + 3) * XS + sc] * sI[cc + 3];
            __nv_bfloat162 lo = __floats2bfloat162_rn(f0, f1);
            __nv_bfloat162 hi = __floats2bfloat162_rn(f2, f3);
            uint2 o; o.x = *(uint32_t*)&lo; o.y = *(uint32_t*)&hi;
            *(uint2*)&g_Mt[(size_t)(128 + dt * 64 + rr) * NN + kb + cc] = o;
        }
    }
}

__device__ __forceinline__ void prep_ptile(const float* __restrict__ Pr,
                                           char* dynsm, int pt) {
    int t = threadIdx.x;
    int tx = t & 15;
    int ty2 = t >> 4;                  // 0..31
    float (*tt65)[65] = (float(*)[65])dynsm;
    int kb = (pt >> 1) * 64;
    int pb = (pt & 1) * 64;
    #pragma unroll
    for (int r = ty2; r < 64; r += 32) {
        float4 v = *(const float4*)&Pr[(size_t)(kb + r) * PP + pb + tx * 4];
        tt65[r][tx * 4 + 0] = v.x;
        tt65[r][tx * 4 + 1] = v.y;
        tt65[r][tx * 4 + 2] = v.z;
        tt65[r][tx * 4 + 3] = v.w;
    }
    __syncthreads();
    #pragma unroll
    for (int rr = ty2; rr < 64; rr += 32) {
        int cc = tx * 4;
        __nv_bfloat162 lo = __floats2bfloat162_rn(tt65[cc + 0][rr], tt65[cc + 1][rr]);
        __nv_bfloat162 hi = __floats2bfloat162_rn(tt65[cc + 2][rr], tt65[cc + 3][rr]);
        uint2 o; o.x = *(uint32_t*)&lo; o.y = *(uint32_t*)&hi;
        *(uint2*)&g_Mt[(size_t)(pb + rr) * NN + kb + cc] = o;
    }
}

// ---- GEMM body: R11 geometry, K-half per CTA, partial handoff ---------------
template <bool GRAM>
__device__ __forceinline__ void gemm_body(const float* __restrict__ Af32,
                                          const __nv_bfloat16* __restrict__ Abf,
                                          const __nv_bfloat16* __restrict__ Bbf,
                                          const float* __restrict__ Pr,
                                          const float* __restrict__ W,
                                          int r_base, int c_base,
                                          int pair, int kh,
                                          __nv_bfloat16* sAb, __nv_bfloat16* sBb) {
    int tid  = threadIdx.x;
    int wid  = tid >> 5;
    int lane = tid & 31;
    int gid  = lane >> 2;
    int tid4 = lane & 3;
    int wm   = wid >> 2;
    int wn   = wid & 3;

    int lrow = (lane & 7) + ((lane >> 3) & 1) * 8;
    int lk8  = (lane >> 4) * 8;

    uint32_t sA_u0 = smem_u32(sAb);
    uint32_t sB_u0 = smem_u32(sBb);

    int kbase = kh * KH;

    float4 rA[2];
    uint4  rAg;
    uint4  rB[2];

    auto load_regs = [&](int it) {
        int k0 = kbase + it * KT;
        #pragma unroll
        for (int q = 0; q < 2; q++) {
            int c = tid + q * 512;
            if (!GRAM)
                rA[q] = *(const float4*)&Af32[(size_t)(c >> 4) * NN + k0 + (c & 15) * 4];
            rB[q] = *(const uint4*)&Bbf[(size_t)(c >> 3) * NN + k0 + (c & 7) * 8];
        }
        if (GRAM)
            rAg = *(const uint4*)&Abf[(size_t)(tid >> 3) * NN + k0 + (tid & 7) * 8];
    };
    auto store_tile = [&](int buf) {
        __nv_bfloat16* sA = sAb + buf * SA_STAGE;
        __nv_bfloat16* sB = sBb + buf * SB_STAGE;
        if (!GRAM) {
            #pragma unroll
            for (int q = 0; q < 2; q++) {
                int c = tid + q * 512;
                __nv_bfloat162 lo = __floats2bfloat162_rn(rA[q].x, rA[q].y);
                __nv_bfloat162 hi = __floats2bfloat162_rn(rA[q].z, rA[q].w);
                uint2 o; o.x = *(uint32_t*)&lo; o.y = *(uint32_t*)&hi;
                *(uint2*)&sA[(c >> 4) * APAD + (c & 15) * 4] = o;
            }
        } else {
            *(uint4*)&sA[(tid >> 3) * APAD + (tid & 7) * 8] = rAg;
        }
        #pragma unroll
        for (int q = 0; q < 2; q++) {
            int c = tid + q * 512;
            *(uint4*)&sB[(c >> 3) * APAD + (c & 7) * 8] = rB[q];
        }
    };

    float acc[4][4] = {};

    load_regs(0);
    store_tile(0);
    load_regs(1);
    __syncthreads();

    for (int it = 0; it < NIT; it++) {
        if (it + 1 < NIT) store_tile((it + 1) & 1);
        if (it + 2 < NIT) load_regs(it + 2);

        uint32_t aU = sA_u0 + (it & 1) * (SA_STAGE * 2);
        uint32_t bU = sB_u0 + (it & 1) * (SB_STAGE * 2);

        #pragma unroll
        for (int kk = 0; kk < KT; kk += 16) {
            uint32_t a0, a1, a2, a3;
            ldmx4(a0, a1, a2, a3,
                  aU + ((wm * 16 + lrow) * APAD + kk + lk8) * 2);
            #pragma unroll
            for (int nj = 0; nj < 2; nj++) {
                uint32_t b0, b1, b2, b3;
                ldmx4(b0, b1, b2, b3,
                      bU + ((wn * 32 + nj * 16 + lrow) * APAD + kk + lk8) * 2);
                mma_bf16(acc[nj * 2 + 0], a0, a1, a2, a3, b0, b2);
                mma_bf16(acc[nj * 2 + 1], a0, a1, a2, a3, b1, b3);
            }
        }
        __syncthreads();
    }

    float* part = g_Spart + (size_t)pair * 8192 + tid * 16;

    if (kh == 1) {
        // publish partial tile, then flag
        #pragma unroll
        for (int i = 0; i < 4; i++)
            *(float4*)&part[i * 4] = *(float4*)acc[i];
        __threadfence();
        __syncthreads();
        if (tid == 0) atomicExch(&g_pflag[pair], 1u);
        return;   // no epilogue for kh=1
    }

    // kh == 0: wait for partner's partial, combine
    if (tid == 0) {
        while (atomicAdd(&g_pflag[pair], 0u) == 0u) { }
    }
    __syncthreads();
    __threadfence();
    #pragma unroll
    for (int i = 0; i < 4; i++) {
        float4 p = *(const float4*)&part[i * 4];
        acc[i][0] += p.x; acc[i][1] += p.y; acc[i][2] += p.z; acc[i][3] += p.w;
    }
    if (tid == 0) g_pflag[pair] = 0u;   // self-reset for next replay

    float s = 0.0f;
    #pragma unroll
    for (int ni = 0; ni < 4; ni++) {
        int col = wn * 32 + ni * 8 + tid4 * 2;
        int m0  = wm * 16 + gid;
        if (!GRAM) {
            int m = r_base + m0;
            float p00 = Pr[(size_t)m * PP + col];
            float p01 = Pr[(size_t)m * PP + col + 1];
            float p10 = Pr[(size_t)(m + 8) * PP + col];
            float p11 = Pr[(size_t)(m + 8) * PP + col + 1];
            float d0 = p00 - acc[ni][0];
            float d1 = p01 - acc[ni][1];
            float d2 = p10 - acc[ni][2];
            float d3 = p11 - acc[ni][3];
            s += d0 * d0 + d1 * d1 + d2 * d2 + d3 * d3;
            float w00 = W[(size_t)m * PP + col];
            float w01 = W[(size_t)m * PP + col + 1];
            float w10 = W[(size_t)(m + 8) * PP + col];
            float w11 = W[(size_t)(m + 8) * PP + col + 1];
            float e0 = p00 - w00, e1 = p01 - w01, e2 = p10 - w10, e3 = p11 - w11;
            s += e0 * e0 + e1 * e1 + e2 * e2 + e3 * e3;
        } else {
            int r0g = r_base + m0;
            int r1g = r0g + 8;
            int c0g = c_base + col;
            int c1g = c0g + 1;
            float s00 = ((r0g < 128) == (c0g < 128)) ? 1.0f : -1.0f;
            float s01 = ((r0g < 128) == (c1g < 128)) ? 1.0f : -1.0f;
            float s10 = ((r1g < 128) == (c0g < 128)) ? 1.0f : -1.0f;
            float s11 = ((r1g < 128) == (c1g < 128)) ? 1.0f : -1.0f;
            s += s00 * acc[ni][0] * acc[ni][0] + s01 * acc[ni][1] * acc[ni][1]
               + s10 * acc[ni][2] * acc[ni][2] + s11 * acc[ni][3] * acc[ni][3];
        }
    }
    s = block_reduce_sum(s);
    if (tid == 0) atomicAdd(&g_acc[GRAM ? 0 : 1], (double)s);
}

// ---------------------------------------------------------------------------
__global__ void __launch_bounds__(512, 2) k_all(const float* __restrict__ A,
                                                const float* __restrict__ Pr,
                                                const float* __restrict__ X,
                                                const float* __restrict__ W,
                                                float* __restrict__ out) {
    extern __shared__ __align__(16) char dynsm[];
    int bid = blockIdx.x;
    int tid = threadIdx.x;

    // ---- phase 1: prep (tasks strided over 292 resident CTAs) ----
    if (bid == 0 && tid < 2) g_acc[tid] = 0.0;
    for (int task = bid; task < PREP_TASKS; task += GRID_MAIN) {
        if (task < 128) prep_xslab(X, dynsm, task);
        else            prep_ptile(Pr, dynsm, task - 128);
        __syncthreads();
    }

    // ---- grid barrier (all 292 CTAs resident: occ forced to 2/SM) ----
    __threadfence();
    __syncthreads();
    if (tid == 0) {
        atomicAdd(&g_sync, 1u);
        while (atomicAdd(&g_sync, 0u) < GRID_MAIN) { }
    }
    __syncthreads();
    __threadfence();

    // ---- phase 2: GEMM (K-split-2 across CTA pairs) ----
    __nv_bfloat16* sAb = (__nv_bfloat16*)dynsm;
    __nv_bfloat16* sBb = (__nv_bfloat16*)(dynsm + SA_STAGE * 2 * 2);

    int pair = bid >> 1;
    int kh   = bid & 1;

    if (pair < STRUCT_PAIRS) {
        gemm_body<false>(A + (size_t)pair * 64 * NN, nullptr, g_Mt, Pr, W,
                         pair * 64, 0, pair, kh, sAb, sBb);
    } else {
        int g = pair - STRUCT_PAIRS;
        int rblk = g / 3, cblk = g % 3;
        gemm_body<true>(nullptr,
                        g_Mt + (size_t)(rblk * 64) * NN,
                        g_Mt + (size_t)(cblk * 128) * NN,
                        Pr, nullptr, rblk * 64, cblk * 128, pair, kh, sAb, sBb);
    }

    // ---- finisher ----
    __shared__ unsigned int s_ticket;
    __threadfence();
    if (tid == 0) s_ticket = atomicAdd(&g_done, 1u);
    __syncthreads();
    if (s_ticket == GRID_MAIN - 1) {
        if (tid == 0) {
            double nn = (double)NN * (double)NN;
            double np = (double)NN * (double)PP;
            out[0] = (float)(g_acc[0] / nn + g_acc[1] / np);
            g_done = 0u;
            g_sync = 0u;
        }
    }
}

// ---------------------------------------------------------------------------
extern "C" void kernel_launch(void* const* d_in, const int* in_sizes, int n_in,
                              void* d_out, int out_size) {
    const float* preds = (const float*)d_in[0];   // [8192, 128]
    const float* emb   = (const float*)d_in[1];   // [8192, 256]
    const float* adj   = (const float*)d_in[2];   // [8192, 8192]
    const float* wts   = (const float*)d_in[3];   // [8192, 128]
    float* out = (float*)d_out;

    // idempotent; capture-safe (no alloc, no sync)
    cudaFuncSetAttribute(k_all, cudaFuncAttributeMaxDynamicSharedMemorySize, SMEM_ALL);

    k_all<<<GRID_MAIN, 512, SMEM_ALL>>>(adj, preds, emb, wts, out);
}

// round 16
// speedup vs baseline: 1.1260x; 1.1260x over previous
#include <cuda_runtime.h>
#include <cuda_bf16.h>
#include <math.h>
#include <stdint.h>

#define NN 8192
#define PP 128
#define DD 256

// ---------------- device scratch (static globals — no runtime alloc) ----------
__device__ __nv_bfloat16 g_Mt[384 * NN];            // Mᵀ bf16: rows 0-127 = Pᵀ, 128-383 = Xnᵀ
__device__ float g_Spart[146 * 64 * 128];           // kh=1 partial tiles (4.8 MB)
__device__ unsigned int g_pflag[146];               // per-tile handoff flags (self-reset)
__device__ double g_acc[2];                         // 0: coherence, 1: structure+weight SSE
__device__ unsigned int g_sync;                     // prep barrier (reset by finisher)
__device__ unsigned int g_done;                     // finisher ticket (reset by finisher)

// ---------------------------------------------------------------------------
__device__ __forceinline__ uint32_t smem_u32(const void* p) {
    return (uint32_t)__cvta_generic_to_shared(p);
}

// block reduce for 128 threads (4 warps)
__device__ __forceinline__ float block_reduce_sum(float v) {
    __shared__ float red[4];
    int lane = threadIdx.x & 31;
    int wid  = threadIdx.x >> 5;
    #pragma unroll
    for (int o = 16; o > 0; o >>= 1) v += __shfl_xor_sync(0xffffffffu, v, o);
    if (lane == 0) red[wid] = v;
    __syncthreads();
    if (wid == 0) {
        v = (lane < 4) ? red[lane] : 0.0f;
        v += __shfl_xor_sync(0xffffffffu, v, 2);
        v += __shfl_xor_sync(0xffffffffu, v, 1);
    }
    return v;
}

// ---------------------------------------------------------------------------
#define STRUCT_PAIRS 128
#define GRAM_PAIRS 18
#define PAIRS (STRUCT_PAIRS + GRAM_PAIRS)     // 146 output tiles
#define GRID_MAIN (PAIRS * 2)                 // 292 CTAs, 2/SM -> all resident

#define NTHREADS 128
#define KH  (NN / 2)                          // 4096 K per CTA
#define KT 64
#define NIT (KH / KT)                         // 64 K-tiles
#define APAD 72
#define SA_STAGE (64 * APAD)
#define SB_STAGE (128 * APAD)
#define SMEM_GEMM ((SA_STAGE + SB_STAGE) * 2 * 2)  // 55296
#define XS 259
#define SMEM_PREPF (64 * XS * 4 + 64 * 4)          // 66560
#define SMEM_ALL (SMEM_PREPF > SMEM_GEMM ? SMEM_PREPF : SMEM_GEMM)

#define PREP_TASKS 384     // 128 X-slabs + 256 P-tiles

__device__ __forceinline__ void ldmx4(uint32_t& r0, uint32_t& r1, uint32_t& r2,
                                      uint32_t& r3, uint32_t addr) {
    asm volatile("ldmatrix.sync.aligned.m8n8.x4.shared.b16 {%0,%1,%2,%3}, [%4];"
                 : "=r"(r0), "=r"(r1), "=r"(r2), "=r"(r3) : "r"(addr));
}
__device__ __forceinline__ void mma_bf16(float* c, uint32_t a0, uint32_t a1,
                                         uint32_t a2, uint32_t a3,
                                         uint32_t b0, uint32_t b1) {
    asm volatile(
        "mma.sync.aligned.m16n8k16.row.col.f32.bf16.bf16.f32 "
        "{%0,%1,%2,%3}, {%4,%5,%6,%7}, {%8,%9}, {%0,%1,%2,%3};"
        : "+f"(c[0]), "+f"(c[1]), "+f"(c[2]), "+f"(c[3])
        : "r"(a0), "r"(a1), "r"(a2), "r"(a3), "r"(b0), "r"(b1));
}

// ---- prep task bodies (128 threads) -----------------------------------------
__device__ __forceinline__ void prep_xslab(const float* __restrict__ X,
                                           char* dynsm, int xs) {
    int t = threadIdx.x;
    int lane = t & 31;
    int wrp  = t >> 5;
    int tx = t & 15;
    int ty = t >> 4;                   // 0..7
    float* tt = (float*)dynsm;
    float* sI = (float*)(dynsm + 64 * XS * 4);
    int kb = xs * 64;

    #pragma unroll 4
    for (int q = 0; q < 32; q++) {
        int c = t + q * NTHREADS;
        int row = c >> 6;
        int col = (c & 63) * 4;
        float4 v = *(const float4*)&X[(size_t)(kb + row) * DD + col];
        tt[row * XS + col + 0] = v.x;
        tt[row * XS + col + 1] = v.y;
        tt[row * XS + col + 2] = v.z;
        tt[row * XS + col + 3] = v.w;
    }
    __syncthreads();

    #pragma unroll
    for (int r16 = 0; r16 < 16; r16++) {
        int row = wrp * 16 + r16;
        float ss = 0.0f;
        #pragma unroll
        for (int j = 0; j < 8; j++) {
            float x = tt[row * XS + lane * 8 + j];
            ss += x * x;
        }
        #pragma unroll
        for (int o = 16; o > 0; o >>= 1) ss += __shfl_xor_sync(0xffffffffu, ss, o);
        if (lane == 0) sI[row] = 1.0f / fmaxf(sqrtf(ss), 1e-8f);
    }
    __syncthreads();

    #pragma unroll
    for (int dt = 0; dt < 4; dt++) {
        #pragma unroll
        for (int rr = ty; rr < 64; rr += 8) {
            int cc = tx * 4;
            int sc = dt * 64 + rr;
            float f0 = tt[(cc + 0) * XS + sc] * sI[cc + 0];
            float f1 = tt[(cc + 1) * XS + sc] * sI[cc + 1];
            float f2 = tt[(cc + 2) * XS + sc] * sI[cc + 2];
            float f3 = tt[(cc + 3) * XS + sc] * sI[cc + 3];
            __nv_bfloat162 lo = __floats2bfloat162_rn(f0, f1);
            __nv_bfloat162 hi = __floats2bfloat162_rn(f2, f3);
            uint2 o; o.x = *(uint32_t*)&lo; o.y = *(uint32_t*)&hi;
            *(uint2*)&g_Mt[(size_t)(128 + dt * 64 + rr) * NN + kb + cc] = o;
        }
    }
}

__device__ __forceinline__ void prep_ptile(const float* __restrict__ Pr,
                                           char* dynsm, int pt) {
    int t = threadIdx.x;
    int tx = t & 15;
    int ty = t >> 4;                   // 0..7
    float (*tt65)[65] = (float(*)[65])dynsm;
    int kb = (pt >> 1) * 64;
    int pb = (pt & 1) * 64;
    #pragma unroll
    for (int r = ty; r < 64; r += 8) {
        float4 v = *(const float4*)&Pr[(size_t)(kb + r) * PP + pb + tx * 4];
        tt65[r][tx * 4 + 0] = v.x;
        tt65[r][tx * 4 + 1] = v.y;
        tt65[r][tx * 4 + 2] = v.z;
        tt65[r][tx * 4 + 3] = v.w;
    }
    __syncthreads();
    #pragma unroll
    for (int rr = ty; rr < 64; rr += 8) {
        int cc = tx * 4;
        __nv_bfloat162 lo = __floats2bfloat162_rn(tt65[cc + 0][rr], tt65[cc + 1][rr]);
        __nv_bfloat162 hi = __floats2bfloat162_rn(tt65[cc + 2][rr], tt65[cc + 3][rr]);
        uint2 o; o.x = *(uint32_t*)&lo; o.y = *(uint32_t*)&hi;
        *(uint2*)&g_Mt[(size_t)(pb + rr) * NN + kb + cc] = o;
    }
}

// ---- GEMM body: 4 warps, 2x2 warp grid, warp tile 32x64, K-half per CTA -----
template <bool GRAM>
__device__ __forceinline__ void gemm_body(const float* __restrict__ Af32,
                                          const __nv_bfloat16* __restrict__ Abf,
                                          const __nv_bfloat16* __restrict__ Bbf,
                                          const float* __restrict__ Pr,
                                          const float* __restrict__ W,
                                          int r_base, int c_base,
                                          int pair, int kh,
                                          __nv_bfloat16* sAb, __nv_bfloat16* sBb) {
    int tid  = threadIdx.x;             // 0..127
    int wid  = tid >> 5;                // 0..3
    int lane = tid & 31;
    int gid  = lane >> 2;
    int tid4 = lane & 3;
    int wm   = wid >> 1;                // 0..1 : 32-row slice
    int wn   = wid & 1;                 // 0..1 : 64-col slice

    int lrow = (lane & 7) + ((lane >> 3) & 1) * 8;
    int lk8  = (lane >> 4) * 8;

    uint32_t sA_u0 = smem_u32(sAb);
    uint32_t sB_u0 = smem_u32(sBb);

    int kbase = kh * KH;

    float4 rA[8];     // structure A staging (fp32)
    uint4  rAg[4];    // gram A staging (bf16)
    uint4  rB[8];

    auto load_regs = [&](int it) {
        int k0 = kbase + it * KT;
        #pragma unroll
        for (int q = 0; q < 8; q++) {
            int c = tid + q * NTHREADS;
            if (!GRAM)
                rA[q] = *(const float4*)&Af32[(size_t)(c >> 4) * NN + k0 + (c & 15) * 4];
            rB[q] = *(const uint4*)&Bbf[(size_t)(c >> 3) * NN + k0 + (c & 7) * 8];
        }
        if (GRAM) {
            #pragma unroll
            for (int q = 0; q < 4; q++) {
                int c = tid + q * NTHREADS;
                rAg[q] = *(const uint4*)&Abf[(size_t)(c >> 3) * NN + k0 + (c & 7) * 8];
            }
        }
    };
    auto store_tile = [&](int buf) {
        __nv_bfloat16* sA = sAb + buf * SA_STAGE;
        __nv_bfloat16* sB = sBb + buf * SB_STAGE;
        if (!GRAM) {
            #pragma unroll
            for (int q = 0; q < 8; q++) {
                int c = tid + q * NTHREADS;
                __nv_bfloat162 lo = __floats2bfloat162_rn(rA[q].x, rA[q].y);
                __nv_bfloat162 hi = __floats2bfloat162_rn(rA[q].z, rA[q].w);
                uint2 o; o.x = *(uint32_t*)&lo; o.y = *(uint32_t*)&hi;
                *(uint2*)&sA[(c >> 4) * APAD + (c & 15) * 4] = o;
            }
        } else {
            #pragma unroll
            for (int q = 0; q < 4; q++) {
                int c = tid + q * NTHREADS;
                *(uint4*)&sA[(c >> 3) * APAD + (c & 7) * 8] = rAg[q];
            }
        }
        #pragma unroll
        for (int q = 0; q < 8; q++) {
            int c = tid + q * NTHREADS;
            *(uint4*)&sB[(c >> 3) * APAD + (c & 7) * 8] = rB[q];
        }
    };

    float acc[2][8][4] = {};   // [mi 16-row tile][nj8 col tile][quad]

    load_regs(0);
    store_tile(0);
    load_regs(1);
    __syncthreads();

    for (int it = 0; it < NIT; it++) {
        if (it + 1 < NIT) store_tile((it + 1) & 1);
        if (it + 2 < NIT) load_regs(it + 2);

        uint32_t aU = sA_u0 + (it & 1) * (SA_STAGE * 2);
        uint32_t bU = sB_u0 + (it & 1) * (SB_STAGE * 2);

        #pragma unroll
        for (int kk = 0; kk < KT; kk += 16) {
            uint32_t a0[4], a1[4];
            ldmx4(a0[0], a0[1], a0[2], a0[3],
                  aU + ((wm * 32 + lrow) * APAD + kk + lk8) * 2);
            ldmx4(a1[0], a1[1], a1[2], a1[3],
                  aU + ((wm * 32 + 16 + lrow) * APAD + kk + lk8) * 2);
            #pragma unroll
            for (int nj = 0; nj < 4; nj++) {
                uint32_t b0, b1, b2, b3;
                ldmx4(b0, b1, b2, b3,
                      bU + ((wn * 64 + nj * 16 + lrow) * APAD + kk + lk8) * 2);
                mma_bf16(acc[0][nj * 2 + 0], a0[0], a0[1], a0[2], a0[3], b0, b2);
                mma_bf16(acc[0][nj * 2 + 1], a0[0], a0[1], a0[2], a0[3], b1, b3);
                mma_bf16(acc[1][nj * 2 + 0], a1[0], a1[1], a1[2], a1[3], b0, b2);
                mma_bf16(acc[1][nj * 2 + 1], a1[0], a1[1], a1[2], a1[3], b1, b3);
            }
        }
        __syncthreads();
    }

    float* part = g_Spart + (size_t)pair * 8192 + tid * 64;

    if (kh == 1) {
        #pragma unroll
        for (int mi = 0; mi < 2; mi++)
            #pragma unroll
            for (int nj = 0; nj < 8; nj++)
                *(float4*)&part[mi * 32 + nj * 4] = *(float4*)acc[mi][nj];
        __threadfence();
        __syncthreads();
        if (tid == 0) atomicExch(&g_pflag[pair], 1u);
        return;
    }

    // kh == 0: wait for partner's partial, combine
    if (tid == 0) {
        while (atomicAdd(&g_pflag[pair], 0u) == 0u) { }
    }
    __syncthreads();
    __threadfence();
    #pragma unroll
    for (int mi = 0; mi < 2; mi++)
        #pragma unroll
        for (int nj = 0; nj < 8; nj++) {
            float4 p = *(const float4*)&part[mi * 32 + nj * 4];
            acc[mi][nj][0] += p.x; acc[mi][nj][1] += p.y;
            acc[mi][nj][2] += p.z; acc[mi][nj][3] += p.w;
        }
    if (tid == 0) g_pflag[pair] = 0u;   // self-reset for next replay

    float s = 0.0f;
    #pragma unroll
    for (int mi = 0; mi < 2; mi++) {
        #pragma unroll
        for (int nj = 0; nj < 8; nj++) {
            int col = wn * 64 + nj * 8 + tid4 * 2;
            int m0  = wm * 32 + mi * 16 + gid;
            if (!GRAM) {
                int m = r_base + m0;
                float p00 = Pr[(size_t)m * PP + col];
                float p01 = Pr[(size_t)m * PP + col + 1];
                float p10 = Pr[(size_t)(m + 8) * PP + col];
                float p11 = Pr[(size_t)(m + 8) * PP + col + 1];
                float d0 = p00 - acc[mi][nj][0];
                float d1 = p01 - acc[mi][nj][1];
                float d2 = p10 - acc[mi][nj][2];
                float d3 = p11 - acc[mi][nj][3];
                s += d0 * d0 + d1 * d1 + d2 * d2 + d3 * d3;
                float w00 = W[(size_t)m * PP + col];
                float w01 = W[(size_t)m * PP + col + 1];
                float w10 = W[(size_t)(m + 8) * PP + col];
                float w11 = W[(size_t)(m + 8) * PP + col + 1];
                float e0 = p00 - w00, e1 = p01 - w01;
                float e2 = p10 - w10, e3 = p11 - w11;
                s += e0 * e0 + e1 * e1 + e2 * e2 + e3 * e3;
            } else {
                int r0g = r_base + m0;
                int r1g = r0g + 8;
                int c0g = c_base + col;
                int c1g = c0g + 1;
                float s00 = ((r0g < 128) == (c0g < 128)) ? 1.0f : -1.0f;
                float s01 = ((r0g < 128) == (c1g < 128)) ? 1.0f : -1.0f;
                float s10 = ((r1g < 128) == (c0g < 128)) ? 1.0f : -1.0f;
                float s11 = ((r1g < 128) == (c1g < 128)) ? 1.0f : -1.0f;
                s += s00 * acc[mi][nj][0] * acc[mi][nj][0]
                   + s01 * acc[mi][nj][1] * acc[mi][nj][1]
                   + s10 * acc[mi][nj][2] * acc[mi][nj][2]
                   + s11 * acc[mi][nj][3] * acc[mi][nj][3];
            }
        }
    }
    s = block_reduce_sum(s);
    if (tid == 0) atomicAdd(&g_acc[GRAM ? 0 : 1], (double)s);
}

// ---------------------------------------------------------------------------
__global__ void __launch_bounds__(NTHREADS, 2) k_all(const float* __restrict__ A,
                                                     const float* __restrict__ Pr,
                                                     const float* __restrict__ X,
                                                     const float* __restrict__ W,
                                                     float* __restrict__ out) {
    extern __shared__ __align__(16) char dynsm[];
    int bid = blockIdx.x;
    int tid = threadIdx.x;

    // ---- phase 1: prep (tasks strided over 292 resident CTAs) ----
    if (bid == 0 && tid < 2) g_acc[tid] = 0.0;
    for (int task = bid; task < PREP_TASKS; task += GRID_MAIN) {
        if (task < 128) prep_xslab(X, dynsm, task);
        else            prep_ptile(Pr, dynsm, task - 128);
        __syncthreads();
    }

    // ---- grid barrier (all 292 CTAs resident: 2/SM by smem+regs budget) ----
    __threadfence();
    __syncthreads();
    if (tid == 0) {
        atomicAdd(&g_sync, 1u);
        while (atomicAdd(&g_sync, 0u) < GRID_MAIN) { }
    }
    __syncthreads();
    __threadfence();

    // ---- phase 2: GEMM (K-split-2 across CTA pairs) ----
    __nv_bfloat16* sAb = (__nv_bfloat16*)dynsm;
    __nv_bfloat16* sBb = (__nv_bfloat16*)(dynsm + SA_STAGE * 2 * 2);

    int pair = bid >> 1;
    int kh   = bid & 1;

    if (pair < STRUCT_PAIRS) {
        gemm_body<false>(A + (size_t)pair * 64 * NN, nullptr, g_Mt, Pr, W,
                         pair * 64, 0, pair, kh, sAb, sBb);
    } else {
        int g = pair - STRUCT_PAIRS;
        int rblk = g / 3, cblk = g % 3;
        gemm_body<true>(nullptr,
                        g_Mt + (size_t)(rblk * 64) * NN,
                        g_Mt + (size_t)(cblk * 128) * NN,
                        Pr, nullptr, rblk * 64, cblk * 128, pair, kh, sAb, sBb);
    }

    // ---- finisher ----
    __shared__ unsigned int s_ticket;
    __threadfence();
    if (tid == 0) s_ticket = atomicAdd(&g_done, 1u);
    __syncthreads();
    if (s_ticket == GRID_MAIN - 1) {
        if (tid == 0) {
            double nn = (double)NN * (double)NN;
            double np = (double)NN * (double)PP;
            out[0] = (float)(g_acc[0] / nn + g_acc[1] / np);
            g_done = 0u;
            g_sync = 0u;
        }
    }
}

// ---------------------------------------------------------------------------
extern "C" void kernel_launch(void* const* d_in, const int* in_sizes, int n_in,
                              void* d_out, int out_size) {
    const float* preds = (const float*)d_in[0];   // [8192, 128]
    const float* emb   = (const float*)d_in[1];   // [8192, 256]
    const float* adj   = (const float*)d_in[2];   // [8192, 8192]
    const float* wts   = (const float*)d_in[3];   // [8192, 128]
    float* out = (float*)d_out;

    // idempotent; capture-safe (no alloc, no sync)
    cudaFuncSetAttribute(k_all, cudaFuncAttributeMaxDynamicSharedMemorySize, SMEM_ALL);

    k_all<<<GRID_MAIN, NTHREADS, SMEM_ALL>>>(adj, preds, emb, wts, out);
}

// round 17
// speedup vs baseline: 1.1292x; 1.0029x over previous
#include <cuda_runtime.h>
#include <cuda_bf16.h>
#include <math.h>
#include <stdint.h>

#define NN 8192
#define PP 128
#define DD 256

// ---------------- device scratch (static globals — no runtime alloc) ----------
__device__ __nv_bfloat16 g_Mt[384 * NN];            // Mᵀ bf16: rows 0-127 = Pᵀ, 128-383 = Xnᵀ
__device__ float g_Spart[146 * 64 * 128];           // kh=1 partial tiles (4.8 MB)
__device__ unsigned int g_pflag[146];               // per-tile handoff flags (self-reset)
__device__ double g_acc[2];                         // 0: coherence, 1: structure+weight SSE
__device__ unsigned int g_sync;                     // prep barrier (reset by finisher)
__device__ unsigned int g_done;                     // finisher ticket (reset by finisher)

// ---------------------------------------------------------------------------
__device__ __forceinline__ uint32_t smem_u32(const void* p) {
    return (uint32_t)__cvta_generic_to_shared(p);
}

// block reduce for 256 threads (8 warps)
__device__ __forceinline__ float block_reduce_sum(float v) {
    __shared__ float red[8];
    int lane = threadIdx.x & 31;
    int wid  = threadIdx.x >> 5;
    #pragma unroll
    for (int o = 16; o > 0; o >>= 1) v += __shfl_xor_sync(0xffffffffu, v, o);
    if (lane == 0) red[wid] = v;
    __syncthreads();
    if (wid == 0) {
        v = (lane < 8) ? red[lane] : 0.0f;
        #pragma unroll
        for (int o = 4; o > 0; o >>= 1) v += __shfl_xor_sync(0xffffffffu, v, o);
    }
    return v;
}

// ---------------------------------------------------------------------------
#define STRUCT_PAIRS 128
#define GRAM_PAIRS 18
#define PAIRS (STRUCT_PAIRS + GRAM_PAIRS)     // 146 output tiles
#define GRID_MAIN (PAIRS * 2)                 // 292 CTAs, 2/SM -> all resident

#define NTHREADS 256
#define KH  (NN / 2)                          // 4096 K per CTA
#define KT 64
#define NIT (KH / KT)                         // 64 K-tiles
#define APAD 72
#define SA_STAGE (64 * APAD)
#define SB_STAGE (128 * APAD)
#define SMEM_GEMM ((SA_STAGE + SB_STAGE) * 2 * 2)  // 55296
#define XS 259
#define SMEM_PREPF (64 * XS * 4 + 64 * 4)          // 66560
#define SMEM_ALL (SMEM_PREPF > SMEM_GEMM ? SMEM_PREPF : SMEM_GEMM)

#define PREP_TASKS 384     // 128 X-slabs + 256 P-tiles

__device__ __forceinline__ void ldmx4(uint32_t& r0, uint32_t& r1, uint32_t& r2,
                                      uint32_t& r3, uint32_t addr) {
    asm volatile("ldmatrix.sync.aligned.m8n8.x4.shared.b16 {%0,%1,%2,%3}, [%4];"
                 : "=r"(r0), "=r"(r1), "=r"(r2), "=r"(r3) : "r"(addr));
}
__device__ __forceinline__ void mma_bf16(float* c, uint32_t a0, uint32_t a1,
                                         uint32_t a2, uint32_t a3,
                                         uint32_t b0, uint32_t b1) {
    asm volatile(
        "mma.sync.aligned.m16n8k16.row.col.f32.bf16.bf16.f32 "
        "{%0,%1,%2,%3}, {%4,%5,%6,%7}, {%8,%9}, {%0,%1,%2,%3};"
        : "+f"(c[0]), "+f"(c[1]), "+f"(c[2]), "+f"(c[3])
        : "r"(a0), "r"(a1), "r"(a2), "r"(a3), "r"(b0), "r"(b1));
}

// ---- prep task bodies (256 threads) -----------------------------------------
__device__ __forceinline__ void prep_xslab(const float* __restrict__ X,
                                           char* dynsm, int xs) {
    int t = threadIdx.x;
    int lane = t & 31;
    int wrp  = t >> 5;
    int tx = t & 15;
    int ty2 = t >> 4;                  // 0..15
    float* tt = (float*)dynsm;
    float* sI = (float*)(dynsm + 64 * XS * 4);
    int kb = xs * 64;

    #pragma unroll
    for (int q = 0; q < 16; q++) {
        int c = t + q * NTHREADS;
        int row = c >> 6;
        int col = (c & 63) * 4;
        float4 v = *(const float4*)&X[(size_t)(kb + row) * DD + col];
        tt[row * XS + col + 0] = v.x;
        tt[row * XS + col + 1] = v.y;
        tt[row * XS + col + 2] = v.z;
        tt[row * XS + col + 3] = v.w;
    }
    __syncthreads();

    #pragma unroll
    for (int r8 = 0; r8 < 8; r8++) {
        int row = wrp * 8 + r8;
        float ss = 0.0f;
        #pragma unroll
        for (int j = 0; j < 8; j++) {
            float x = tt[row * XS + lane * 8 + j];
            ss += x * x;
        }
        #pragma unroll
        for (int o = 16; o > 0; o >>= 1) ss += __shfl_xor_sync(0xffffffffu, ss, o);
        if (lane == 0) sI[row] = 1.0f / fmaxf(sqrtf(ss), 1e-8f);
    }
    __syncthreads();

    #pragma unroll
    for (int dt = 0; dt < 4; dt++) {
        #pragma unroll
        for (int rr = ty2; rr < 64; rr += 16) {
            int cc = tx * 4;
            int sc = dt * 64 + rr;
            float f0 = tt[(cc + 0) * XS + sc] * sI[cc + 0];
            float f1 = tt[(cc + 1) * XS + sc] * sI[cc + 1];
            float f2 = tt[(cc + 2) * XS + sc] * sI[cc + 2];
            float f3 = tt[(cc + 3) * XS + sc] * sI[cc + 3];
            __nv_bfloat162 lo = __floats2bfloat162_rn(f0, f1);
            __nv_bfloat162 hi = __floats2bfloat162_rn(f2, f3);
            uint2 o; o.x = *(uint32_t*)&lo; o.y = *(uint32_t*)&hi;
            *(uint2*)&g_Mt[(size_t)(128 + dt * 64 + rr) * NN + kb + cc] = o;
        }
    }
}

__device__ __forceinline__ void prep_ptile(const float* __restrict__ Pr,
                                           char* dynsm, int pt) {
    int t = threadIdx.x;
    int tx = t & 15;
    int ty2 = t >> 4;                  // 0..15
    float (*tt65)[65] = (float(*)[65])dynsm;
    int kb = (pt >> 1) * 64;
    int pb = (pt & 1) * 64;
    #pragma unroll
    for (int r = ty2; r < 64; r += 16) {
        float4 v = *(const float4*)&Pr[(size_t)(kb + r) * PP + pb + tx * 4];
        tt65[r][tx * 4 + 0] = v.x;
        tt65[r][tx * 4 + 1] = v.y;
        tt65[r][tx * 4 + 2] = v.z;
        tt65[r][tx * 4 + 3] = v.w;
    }
    __syncthreads();
    #pragma unroll
    for (int rr = ty2; rr < 64; rr += 16) {
        int cc = tx * 4;
        __nv_bfloat162 lo = __floats2bfloat162_rn(tt65[cc + 0][rr], tt65[cc + 1][rr]);
        __nv_bfloat162 hi = __floats2bfloat162_rn(tt65[cc + 2][rr], tt65[cc + 3][rr]);
        uint2 o; o.x = *(uint32_t*)&lo; o.y = *(uint32_t*)&hi;
        *(uint2*)&g_Mt[(size_t)(pb + rr) * NN + kb + cc] = o;
    }
}

// ---- GEMM body: 8 warps 2x4, warp tile 32x32, K-half per CTA ----------------
template <bool GRAM>
__device__ __forceinline__ void gemm_body(const float* __restrict__ Af32,
                                          const __nv_bfloat16* __restrict__ Abf,
                                          const __nv_bfloat16* __restrict__ Bbf,
                                          const float* __restrict__ Pr,
                                          const float* __restrict__ W,
                                          int r_base, int c_base,
                                          int pair, int kh,
                                          __nv_bfloat16* sAb, __nv_bfloat16* sBb) {
    int tid  = threadIdx.x;             // 0..255
    int wid  = tid >> 5;                // 0..7
    int lane = tid & 31;
    int gid  = lane >> 2;
    int tid4 = lane & 3;
    int wm   = wid >> 2;                // 0..1 : 32-row slice
    int wn   = wid & 3;                 // 0..3 : 32-col slice

    int lrow = (lane & 7) + ((lane >> 3) & 1) * 8;
    int lk8  = (lane >> 4) * 8;

    uint32_t sA_u0 = smem_u32(sAb);
    uint32_t sB_u0 = smem_u32(sBb);

    int kbase = kh * KH;

    float4 rA[4];
    uint4  rAg[2];
    uint4  rB[4];

    auto load_regs = [&](int it) {
        int k0 = kbase + it * KT;
        #pragma unroll
        for (int q = 0; q < 4; q++) {
            int c = tid + q * NTHREADS;
            if (!GRAM)
                rA[q] = *(const float4*)&Af32[(size_t)(c >> 4) * NN + k0 + (c & 15) * 4];
            rB[q] = *(const uint4*)&Bbf[(size_t)(c >> 3) * NN + k0 + (c & 7) * 8];
        }
        if (GRAM) {
            #pragma unroll
            for (int q = 0; q < 2; q++) {
                int c = tid + q * NTHREADS;
                rAg[q] = *(const uint4*)&Abf[(size_t)(c >> 3) * NN + k0 + (c & 7) * 8];
            }
        }
    };
    auto store_tile = [&](int buf) {
        __nv_bfloat16* sA = sAb + buf * SA_STAGE;
        __nv_bfloat16* sB = sBb + buf * SB_STAGE;
        if (!GRAM) {
            #pragma unroll
            for (int q = 0; q < 4; q++) {
                int c = tid + q * NTHREADS;
                __nv_bfloat162 lo = __floats2bfloat162_rn(rA[q].x, rA[q].y);
                __nv_bfloat162 hi = __floats2bfloat162_rn(rA[q].z, rA[q].w);
                uint2 o; o.x = *(uint32_t*)&lo; o.y = *(uint32_t*)&hi;
                *(uint2*)&sA[(c >> 4) * APAD + (c & 15) * 4] = o;
            }
        } else {
            #pragma unroll
            for (int q = 0; q < 2; q++) {
                int c = tid + q * NTHREADS;
                *(uint4*)&sA[(c >> 3) * APAD + (c & 7) * 8] = rAg[q];
            }
        }
        #pragma unroll
        for (int q = 0; q < 4; q++) {
            int c = tid + q * NTHREADS;
            *(uint4*)&sB[(c >> 3) * APAD + (c & 7) * 8] = rB[q];
        }
    };

    float acc[2][4][4] = {};   // [mi 16-row half][nj8 col tile][quad]

    load_regs(0);
    store_tile(0);
    load_regs(1);
    __syncthreads();

    for (int it = 0; it < NIT; it++) {
        if (it + 1 < NIT) store_tile((it + 1) & 1);
        if (it + 2 < NIT) load_regs(it + 2);

        uint32_t aU = sA_u0 + (it & 1) * (SA_STAGE * 2);
        uint32_t bU = sB_u0 + (it & 1) * (SB_STAGE * 2);

        #pragma unroll
        for (int kk = 0; kk < KT; kk += 16) {
            uint32_t a0[4], a1[4];
            ldmx4(a0[0], a0[1], a0[2], a0[3],
                  aU + ((wm * 32 + lrow) * APAD + kk + lk8) * 2);
            ldmx4(a1[0], a1[1], a1[2], a1[3],
                  aU + ((wm * 32 + 16 + lrow) * APAD + kk + lk8) * 2);
            #pragma unroll
            for (int nj = 0; nj < 2; nj++) {
                uint32_t b0, b1, b2, b3;
                ldmx4(b0, b1, b2, b3,
                      bU + ((wn * 32 + nj * 16 + lrow) * APAD + kk + lk8) * 2);
                mma_bf16(acc[0][nj * 2 + 0], a0[0], a0[1], a0[2], a0[3], b0, b2);
                mma_bf16(acc[0][nj * 2 + 1], a0[0], a0[1], a0[2], a0[3], b1, b3);
                mma_bf16(acc[1][nj * 2 + 0], a1[0], a1[1], a1[2], a1[3], b0, b2);
                mma_bf16(acc[1][nj * 2 + 1], a1[0], a1[1], a1[2], a1[3], b1, b3);
            }
        }
        __syncthreads();
    }

    float* part = g_Spart + (size_t)pair * 8192 + tid * 32;

    if (kh == 1) {
        #pragma unroll
        for (int mi = 0; mi < 2; mi++)
            #pragma unroll
            for (int nj = 0; nj < 4; nj++)
                *(float4*)&part[mi * 16 + nj * 4] = *(float4*)acc[mi][nj];
        __threadfence();
        __syncthreads();
        if (tid == 0) atomicExch(&g_pflag[pair], 1u);
        return;
    }

    // kh == 0: wait for partner's partial, combine
    if (tid == 0) {
        while (atomicAdd(&g_pflag[pair], 0u) == 0u) { }
    }
    __syncthreads();
    __threadfence();
    #pragma unroll
    for (int mi = 0; mi < 2; mi++)
        #pragma unroll
        for (int nj = 0; nj < 4; nj++) {
            float4 p = *(const float4*)&part[mi * 16 + nj * 4];
            acc[mi][nj][0] += p.x; acc[mi][nj][1] += p.y;
            acc[mi][nj][2] += p.z; acc[mi][nj][3] += p.w;
        }
    if (tid == 0) g_pflag[pair] = 0u;   // self-reset for next replay

    float s = 0.0f;
    #pragma unroll
    for (int mi = 0; mi < 2; mi++) {
        #pragma unroll
        for (int nj = 0; nj < 4; nj++) {
            int col = wn * 32 + nj * 8 + tid4 * 2;
            int m0  = wm * 32 + mi * 16 + gid;
            if (!GRAM) {
                int m = r_base + m0;
                float p00 = Pr[(size_t)m * PP + col];
                float p01 = Pr[(size_t)m * PP + col + 1];
                float p10 = Pr[(size_t)(m + 8) * PP + col];
                float p11 = Pr[(size_t)(m + 8) * PP + col + 1];
                float d0 = p00 - acc[mi][nj][0];
                float d1 = p01 - acc[mi][nj][1];
                float d2 = p10 - acc[mi][nj][2];
                float d3 = p11 - acc[mi][nj][3];
                s += d0 * d0 + d1 * d1 + d2 * d2 + d3 * d3;
                float w00 = W[(size_t)m * PP + col];
                float w01 = W[(size_t)m * PP + col + 1];
                float w10 = W[(size_t)(m + 8) * PP + col];
                float w11 = W[(size_t)(m + 8) * PP + col + 1];
                float e0 = p00 - w00, e1 = p01 - w01;
                float e2 = p10 - w10, e3 = p11 - w11;
                s += e0 * e0 + e1 * e1 + e2 * e2 + e3 * e3;
            } else {
                int r0g = r_base + m0;
                int r1g = r0g + 8;
                int c0g = c_base + col;
                int c1g = c0g + 1;
                float s00 = ((r0g < 128) == (c0g < 128)) ? 1.0f : -1.0f;
                float s01 = ((r0g < 128) == (c1g < 128)) ? 1.0f : -1.0f;
                float s10 = ((r1g < 128) == (c0g < 128)) ? 1.0f : -1.0f;
                float s11 = ((r1g < 128) == (c1g < 128)) ? 1.0f : -1.0f;
                s += s00 * acc[mi][nj][0] * acc[mi][nj][0]
                   + s01 * acc[mi][nj][1] * acc[mi][nj][1]
                   + s10 * acc[mi][nj][2] * acc[mi][nj][2]
                   + s11 * acc[mi][nj][3] * acc[mi][nj][3];
            }
        }
    }
    s = block_reduce_sum(s);
    if (tid == 0) atomicAdd(&g_acc[GRAM ? 0 : 1], (double)s);
}

// ---------------------------------------------------------------------------
__global__ void __launch_bounds__(NTHREADS, 2) k_all(const float* __restrict__ A,
                                                     const float* __restrict__ Pr,
                                                     const float* __restrict__ X,
                                                     const float* __restrict__ W,
                                                     float* __restrict__ out) {
    extern __shared__ __align__(16) char dynsm[];
    int bid = blockIdx.x;
    int tid = threadIdx.x;

    // ---- phase 1: prep (tasks strided over 292 resident CTAs) ----
    if (bid == 0 && tid < 2) g_acc[tid] = 0.0;
    for (int task = bid; task < PREP_TASKS; task += GRID_MAIN) {
        if (task < 128) prep_xslab(X, dynsm, task);
        else            prep_ptile(Pr, dynsm, task - 128);
        __syncthreads();
    }

    // ---- grid barrier (all 292 CTAs resident: 2/SM by smem+regs budget) ----
    __threadfence();
    __syncthreads();
    if (tid == 0) {
        atomicAdd(&g_sync, 1u);
        while (atomicAdd(&g_sync, 0u) < GRID_MAIN) { }
    }
    __syncthreads();
    __threadfence();

    // ---- phase 2: GEMM (K-split-2 across CTA pairs) ----
    __nv_bfloat16* sAb = (__nv_bfloat16*)dynsm;
    __nv_bfloat16* sBb = (__nv_bfloat16*)(dynsm + SA_STAGE * 2 * 2);

    int pair = bid >> 1;
    int kh   = bid & 1;

    if (pair < STRUCT_PAIRS) {
        gemm_body<false>(A + (size_t)pair * 64 * NN, nullptr, g_Mt, Pr, W,
                         pair * 64, 0, pair, kh, sAb, sBb);
    } else {
        int g = pair - STRUCT_PAIRS;
        int rblk = g / 3, cblk = g % 3;
        gemm_body<true>(nullptr,
                        g_Mt + (size_t)(rblk * 64) * NN,
                        g_Mt + (size_t)(cblk * 128) * NN,
                        Pr, nullptr, rblk * 64, cblk * 128, pair, kh, sAb, sBb);
    }

    // ---- finisher ----
    __shared__ unsigned int s_ticket;
    __threadfence();
    if (tid == 0) s_ticket = atomicAdd(&g_done, 1u);
    __syncthreads();
    if (s_ticket == GRID_MAIN - 1) {
        if (tid == 0) {
            double nn = (double)NN * (double)NN;
            double np = (double)NN * (double)PP;
            out[0] = (float)(g_acc[0] / nn + g_acc[1] / np);
            g_done = 0u;
            g_sync = 0u;
        }
    }
}

// ---------------------------------------------------------------------------
extern "C" void kernel_launch(void* const* d_in, const int* in_sizes, int n_in,
                              void* d_out, int out_size) {
    const float* preds = (const float*)d_in[0];   // [8192, 128]
    const float* emb   = (const float*)d_in[1];   // [8192, 256]
    const float* adj   = (const float*)d_in[2];   // [8192, 8192]
    const float* wts   = (const float*)d_in[3];   // [8192, 128]
    float* out = (float*)d_out;

    // idempotent; capture-safe (no alloc, no sync)
    cudaFuncSetAttribute(k_all, cudaFuncAttributeMaxDynamicSharedMemorySize, SMEM_ALL);

    k_all<<<GRID_MAIN, NTHREADS, SMEM_ALL>>>(adj, preds, emb, wts, out);
}